// round 14
// baseline (speedup 1.0000x reference)
#include <cuda_runtime.h>

// LIF membrane recurrence — FINAL.
//   mem[0] = x[0]; mem[t] = 0.25 * mem[t-1] * (1 - spike[t-1]) + x[t]
//   spike[t] = (mem[t] > 0.5)
// x: (8, 32, 128, 32, 32) fp32. Recurrence only along t; 4,194,304 independent
// sites. 134 MB read + 134 MB write, zero reuse -> pure HBM-bound.
//
// Session verdict after 13 rounds: this shape IS the hardware floor.
// Seven samples: 36.06-36.74us kernel, DRAM 74-75%, effective ~7.4 TB/s
// (incl. deferred L2 writeback of the output stream) = saturated mixed-stream
// HBM bandwidth. Rejected alternatives (kernel time):
//   .cs ld+st / .cg loads          44.7 / 45.3us  (default caching load-bearing)
//   sw pipeline (MLP 8->2)         38.1us         (loop overhead > gain)
//   tile x2 / block 512            37.2 / 36.1us  (neutral, DRAM-invariant)
//   v8.b32 256-bit ld/st           41.9us         (76 regs -> occ 29%)
//   persistent 1-wave grid-stride  38.6us         (back-edge serialization)
//   MaxL1 carveout hint            36.3us         (neutral)
// Compute pipes <9%, tensor 0%, occ ~81%: traffic is mandatory and
// incompressible; no further lever exists.

#define T_STEPS 8
#define INNER   (32 * 128 * 32 * 32)   // 4,194,304 elements per timestep
#define INNER4  (INNER / 4)            // 1,048,576 float4 sites

__global__ void lif_kernel(const float4* __restrict__ x, float4* __restrict__ out) {
    int i = blockIdx.x * blockDim.x + threadIdx.x;
    if (i >= INNER4) return;

    // Front-batch all 8 timestep loads (independent -> MLP=8).
    float4 xv[T_STEPS];
#pragma unroll
    for (int t = 0; t < T_STEPS; ++t) {
        xv[t] = x[(size_t)t * INNER4 + i];
    }

    const float DECAY = 0.25f;
    const float THR   = 0.5f;

    float m0 = 0.f, m1 = 0.f, m2 = 0.f, m3 = 0.f;
    float s0 = 0.f, s1 = 0.f, s2 = 0.f, s3 = 0.f;

#pragma unroll
    for (int t = 0; t < T_STEPS; ++t) {
        m0 = DECAY * m0 * (1.0f - s0) + xv[t].x;
        m1 = DECAY * m1 * (1.0f - s1) + xv[t].y;
        m2 = DECAY * m2 * (1.0f - s2) + xv[t].z;
        m3 = DECAY * m3 * (1.0f - s3) + xv[t].w;
        s0 = (m0 > THR) ? 1.0f : 0.0f;
        s1 = (m1 > THR) ? 1.0f : 0.0f;
        s2 = (m2 > THR) ? 1.0f : 0.0f;
        s3 = (m3 > THR) ? 1.0f : 0.0f;
        out[(size_t)t * INNER4 + i] = make_float4(s0, s1, s2, s3);
    }
}

extern "C" void kernel_launch(void* const* d_in, const int* in_sizes, int n_in,
                              void* d_out, int out_size) {
    const float4* x = (const float4*)d_in[0];
    float4* out = (float4*)d_out;
    int threads = 256;
    int blocks = (INNER4 + threads - 1) / threads;   // 4096
    lif_kernel<<<blocks, threads>>>(x, out);
}

// round 15
// speedup vs baseline: 1.0261x; 1.0261x over previous
#include <cuda_runtime.h>

// LIF membrane recurrence — FINAL (hardware floor, 8x confirmed).
//   mem[0] = x[0]; mem[t] = 0.25 * mem[t-1] * (1 - spike[t-1]) + x[t]
//   spike[t] = (mem[t] > 0.5)
// x: (8, 32, 128, 32, 32) fp32. Recurrence only along t; 4,194,304 independent
// sites. 134 MB read + 134 MB write, zero reuse -> pure HBM-bound.
//
// Eight samples of this exact binary: 36.06-36.74us kernel, DRAM 74-75%,
// effective ~7.4 TB/s incl. deferred L2 writeback = saturated mixed-stream
// HBM bandwidth. Harness spread 44.10-45.22us for identical binaries = noise.
// Rejected alternatives (kernel time, isolated A/B):
//   .cs ld+st / .cg loads          44.7 / 45.3us  (default caching load-bearing)
//   sw pipeline (MLP 8->2)         38.1us         (back-edge serialization)
//   persistent 1-wave grid-stride  38.6us         (same mechanism)
//   v8.b32 256-bit ld/st           41.9us         (76 regs -> occ 29%)
//   tile x2 / block 512 / MaxL1    36.1-37.2us    (neutral, DRAM-invariant)
// Compute <9%, tensor 0%, occ ~81%: traffic mandatory and incompressible.

#define T_STEPS 8
#define INNER   (32 * 128 * 32 * 32)   // 4,194,304 elements per timestep
#define INNER4  (INNER / 4)            // 1,048,576 float4 sites

__global__ void lif_kernel(const float4* __restrict__ x, float4* __restrict__ out) {
    int i = blockIdx.x * blockDim.x + threadIdx.x;
    if (i >= INNER4) return;

    // Front-batch all 8 timestep loads (independent -> MLP=8).
    float4 xv[T_STEPS];
#pragma unroll
    for (int t = 0; t < T_STEPS; ++t) {
        xv[t] = x[(size_t)t * INNER4 + i];
    }

    const float DECAY = 0.25f;
    const float THR   = 0.5f;

    float m0 = 0.f, m1 = 0.f, m2 = 0.f, m3 = 0.f;
    float s0 = 0.f, s1 = 0.f, s2 = 0.f, s3 = 0.f;

#pragma unroll
    for (int t = 0; t < T_STEPS; ++t) {
        m0 = DECAY * m0 * (1.0f - s0) + xv[t].x;
        m1 = DECAY * m1 * (1.0f - s1) + xv[t].y;
        m2 = DECAY * m2 * (1.0f - s2) + xv[t].z;
        m3 = DECAY * m3 * (1.0f - s3) + xv[t].w;
        s0 = (m0 > THR) ? 1.0f : 0.0f;
        s1 = (m1 > THR) ? 1.0f : 0.0f;
        s2 = (m2 > THR) ? 1.0f : 0.0f;
        s3 = (m3 > THR) ? 1.0f : 0.0f;
        out[(size_t)t * INNER4 + i] = make_float4(s0, s1, s2, s3);
    }
}

extern "C" void kernel_launch(void* const* d_in, const int* in_sizes, int n_in,
                              void* d_out, int out_size) {
    const float4* x = (const float4*)d_in[0];
    float4* out = (float4*)d_out;
    int threads = 256;
    int blocks = (INNER4 + threads - 1) / threads;   // 4096
    lif_kernel<<<blocks, threads>>>(x, out);
}